// round 6
// baseline (speedup 1.0000x reference)
#include <cuda_runtime.h>
#include <math.h>
#include <stdint.h>

// Problem constants
#define CN 50000
#define CE 800000
#define CR 3
#define CT 16

typedef unsigned long long ull;

__device__ __forceinline__ ull fma2(ull a, ull b, ull c) {
    ull d; asm("fma.rn.f32x2 %0, %1, %2, %3;" : "=l"(d) : "l"(a), "l"(b), "l"(c)); return d;
}
__device__ __forceinline__ void unpack2(ull v, float& lo, float& hi) {
    asm("mov.b64 {%0,%1}, %2;" : "=f"(lo), "=f"(hi) : "l"(v));
}

// ---------------- scratch layout (floats) ----------------
constexpr size_t SZ_WCAT = 256 * 128;
constexpr size_t OFF_WCV = 0;
constexpr size_t OFF_WCS = OFF_WCV + SZ_WCAT;
constexpr size_t OFF_BCV = OFF_WCS + SZ_WCAT;
constexpr size_t OFF_BCS = OFF_BCV + 256;
constexpr size_t OFF_HV0 = OFF_BCS + 256;                 // N*64 each
constexpr size_t OFF_HV1 = OFF_HV0 + (size_t)CN * 64;
constexpr size_t OFF_HS0 = OFF_HV1 + (size_t)CN * 64;
constexpr size_t OFF_HS1 = OFF_HS0 + (size_t)CN * 64;
constexpr size_t OFF_CV  = OFF_HS1 + (size_t)CN * 64;
constexpr size_t OFF_CS  = OFF_CV + (size_t)CN * 64;
constexpr size_t OFF_XCAT= OFF_CS + (size_t)CN * 64;      // [xv|xp|xs|xp] N*512
constexpr size_t OFF_BIG = OFF_XCAT + (size_t)CN * 512;   // [hall0..2, xin0..2] N*768
constexpr size_t OFF_P1  = OFF_BIG + (size_t)CN * 768;    // N*128
constexpr size_t OFF_DEG = OFF_P1 + (size_t)CN * 128;     // N
constexpr size_t OFF_DINV= OFF_DEG + CN;                  // N
constexpr size_t OFF_F   = OFF_DINV + CN;                 // N*5*128
constexpr size_t OFF_SC  = OFF_F + (size_t)CN * 640;      // scores N*5
constexpr size_t OFF_RES = OFF_SC + (size_t)CN * 5 + 64;  // N*128
constexpr size_t SCRATCH_TOTAL = OFF_RES + (size_t)CN * 128;

__device__ float g_scratch[SCRATCH_TOTAL];
__device__ int g_csr[CE];
__device__ int g_off[CN + 1];
__device__ int g_cur[CN];

// =====================================================================
// FFMA2 GEMM core, pack-free layout:
//  - A tile in smem as plain floats; a row-PAIR read by one 64-bit load
//    is already a packed (row2i, row2i+1) FFMA2 operand.
//  - B tile stored DUPLICATED: each weight w stored as (w,w); LDS.128
//    yields two ready b-operands.
//  - acc2[ii][j]: rows (ty*8+2ii, +2ii+1) x col (tx*8+j).
// 128x128 output tile, BK=16, double-buffered, 256 threads.
// =====================================================================
#define TILE_COMPUTE2(cur)                                                     \
    _Pragma("unroll")                                                          \
    for (int kk = 0; kk < 16; kk++) {                                          \
        ull a2[4]; ull b2[8];                                                  \
        {                                                                      \
            const ulonglong2* apv = (const ulonglong2*)(&As[cur][kk][ty * 8]); \
            ulonglong2 t0 = apv[0], t1 = apv[1];                               \
            a2[0] = t0.x; a2[1] = t0.y; a2[2] = t1.x; a2[3] = t1.y;            \
            const ulonglong2* wp = (const ulonglong2*)(&Ws2[cur][kk][tx * 16]);\
            ulonglong2 w0 = wp[0], w1 = wp[1], w2_ = wp[2], w3 = wp[3];        \
            b2[0] = w0.x; b2[1] = w0.y; b2[2] = w1.x; b2[3] = w1.y;            \
            b2[4] = w2_.x; b2[5] = w2_.y; b2[6] = w3.x; b2[7] = w3.y;          \
        }                                                                      \
        _Pragma("unroll")                                                      \
        for (int ii = 0; ii < 4; ii++)                                         \
            _Pragma("unroll")                                                  \
            for (int j = 0; j < 8; j++)                                        \
                acc2[ii][j] = fma2(a2[ii], b2[j], acc2[ii][j]);                \
    }

#define STORE_TILE2(buf)                                                                        \
    As[buf][lk+0][lr] = pa0.x; As[buf][lk+1][lr] = pa0.y;                                       \
    As[buf][lk+2][lr] = pa0.z; As[buf][lk+3][lr] = pa0.w;                                       \
    As[buf][lk+0][lr+64] = pa1.x; As[buf][lk+1][lr+64] = pa1.y;                                 \
    As[buf][lk+2][lr+64] = pa1.z; As[buf][lk+3][lr+64] = pa1.w;                                 \
    *(float2*)(&Ws2[buf][lk+0][lr*2])      = make_float2(pw0.x, pw0.x);                         \
    *(float2*)(&Ws2[buf][lk+1][lr*2])      = make_float2(pw0.y, pw0.y);                         \
    *(float2*)(&Ws2[buf][lk+2][lr*2])      = make_float2(pw0.z, pw0.z);                         \
    *(float2*)(&Ws2[buf][lk+3][lr*2])      = make_float2(pw0.w, pw0.w);                         \
    *(float2*)(&Ws2[buf][lk+0][(lr+64)*2]) = make_float2(pw1.x, pw1.x);                         \
    *(float2*)(&Ws2[buf][lk+1][(lr+64)*2]) = make_float2(pw1.y, pw1.y);                         \
    *(float2*)(&Ws2[buf][lk+2][(lr+64)*2]) = make_float2(pw1.z, pw1.z);                         \
    *(float2*)(&Ws2[buf][lk+3][(lr+64)*2]) = make_float2(pw1.w, pw1.w);

// ---------------- generic SGEMM:  C = act(A @ W^T + bias) ----------------
__global__ __launch_bounds__(256, 2) void sgemm_kernel(
    const float* __restrict__ A, int lda, int K1,
    const float* __restrict__ A2, int lda2,
    const float* __restrict__ W,
    const float* __restrict__ bias,
    float* __restrict__ C, int ldc,
    int M, int K, int act)
{
    __shared__ float As[2][16][128];
    __shared__ float Ws2[2][16][256];

    const int bm = blockIdx.y * 128;
    const int bn = blockIdx.x * 128;
    const int tid = threadIdx.x;
    const int lr = tid >> 2;
    const int lk = (tid & 3) << 2;
    const int ty = tid >> 4, tx = tid & 15;

    ull acc2[4][8];
#pragma unroll
    for (int ii = 0; ii < 4; ii++)
#pragma unroll
        for (int j = 0; j < 8; j++) acc2[ii][j] = 0ull;

    int r0 = bm + lr;      r0 = r0 < M ? r0 : (M - 1);
    int r1 = bm + lr + 64; r1 = r1 < M ? r1 : (M - 1);

    float4 pa0, pa1, pw0, pw1;
    {
        int kg = lk;
        pa0 = (kg < K1) ? *(const float4*)(A + (size_t)r0 * lda + kg)
                        : *(const float4*)(A2 + (size_t)r0 * lda2 + (kg - K1));
        pa1 = (kg < K1) ? *(const float4*)(A + (size_t)r1 * lda + kg)
                        : *(const float4*)(A2 + (size_t)r1 * lda2 + (kg - K1));
        pw0 = *(const float4*)(W + (size_t)(bn + lr) * K + kg);
        pw1 = *(const float4*)(W + (size_t)(bn + lr + 64) * K + kg);
    }
    STORE_TILE2(0)
    __syncthreads();

    const int ntiles = K >> 4;
    for (int t = 0; t < ntiles; t++) {
        const int cur = t & 1, nxt = cur ^ 1;
        const bool has = (t + 1) < ntiles;
        if (has) {
            int kg = ((t + 1) << 4) + lk;
            pa0 = (kg < K1) ? *(const float4*)(A + (size_t)r0 * lda + kg)
                            : *(const float4*)(A2 + (size_t)r0 * lda2 + (kg - K1));
            pa1 = (kg < K1) ? *(const float4*)(A + (size_t)r1 * lda + kg)
                            : *(const float4*)(A2 + (size_t)r1 * lda2 + (kg - K1));
            pw0 = *(const float4*)(W + (size_t)(bn + lr) * K + kg);
            pw1 = *(const float4*)(W + (size_t)(bn + lr + 64) * K + kg);
        }
        TILE_COMPUTE2(cur)
        if (has) { STORE_TILE2(nxt) }
        __syncthreads();
    }

    float bs0[8];
    *(float4*)(&bs0[0]) = *(const float4*)(bias + bn + tx * 8);
    *(float4*)(&bs0[4]) = *(const float4*)(bias + bn + tx * 8 + 4);

#pragma unroll
    for (int ii = 0; ii < 4; ii++) {
        float vr0[8], vr1[8];
#pragma unroll
        for (int j = 0; j < 8; j++) unpack2(acc2[ii][j], vr0[j], vr1[j]);
#pragma unroll
        for (int h = 0; h < 2; h++) {
            int m = bm + ty * 8 + 2 * ii + h;
            if (m >= M) continue;
            float* vv = h ? vr1 : vr0;
            float v[8];
#pragma unroll
            for (int j = 0; j < 8; j++) {
                float x = vv[j] + bs0[j];
                if (act == 1)      x = x > 0.f ? x : 0.01f * x;
                else if (act == 2) x = tanhf(x);
                v[j] = x;
            }
            float* cp = C + (size_t)m * ldc + bn + tx * 8;
            *(float4*)(cp)     = *(float4*)(&v[0]);
            *(float4*)(cp + 4) = *(float4*)(&v[4]);
        }
    }
}

static inline void gemm(const float* A, int lda, int K1,
                        const float* A2, int lda2,
                        const float* W, const float* bias,
                        float* C, int ldc, int M, int O, int K, int act)
{
    dim3 grid(O / 128, (M + 127) / 128);
    sgemm_kernel<<<grid, 256>>>(A, lda, K1, A2, lda2, W, bias, C, ldc, M, K, act);
}

// ---------------- score GEMM: score[m] = w2 . tanh(A[m] @ W^T + bias) ----------------
// O = 128 exactly (one column tile); Y never materialized.
__global__ __launch_bounds__(256, 2) void sgemm_score_kernel(
    const float* __restrict__ A, int lda,
    const float* __restrict__ W,
    const float* __restrict__ bias,
    const float* __restrict__ w2,
    float* __restrict__ score,
    int M)
{
    __shared__ float As[2][16][128];
    __shared__ float Ws2[2][16][256];

    const int bm = blockIdx.y * 128;
    const int tid = threadIdx.x;
    const int lr = tid >> 2;
    const int lk = (tid & 3) << 2;
    const int ty = tid >> 4, tx = tid & 15;
    const int K = 128;

    ull acc2[4][8];
#pragma unroll
    for (int ii = 0; ii < 4; ii++)
#pragma unroll
        for (int j = 0; j < 8; j++) acc2[ii][j] = 0ull;

    int r0 = bm + lr;      r0 = r0 < M ? r0 : (M - 1);
    int r1 = bm + lr + 64; r1 = r1 < M ? r1 : (M - 1);

    float4 pa0, pa1, pw0, pw1;
    {
        int kg = lk;
        pa0 = *(const float4*)(A + (size_t)r0 * lda + kg);
        pa1 = *(const float4*)(A + (size_t)r1 * lda + kg);
        pw0 = *(const float4*)(W + (size_t)lr * K + kg);
        pw1 = *(const float4*)(W + (size_t)(lr + 64) * K + kg);
    }
    STORE_TILE2(0)
    __syncthreads();

#pragma unroll
    for (int t = 0; t < 8; t++) {
        const int cur = t & 1, nxt = cur ^ 1;
        const bool has = t < 7;
        if (has) {
            int kg = ((t + 1) << 4) + lk;
            pa0 = *(const float4*)(A + (size_t)r0 * lda + kg);
            pa1 = *(const float4*)(A + (size_t)r1 * lda + kg);
            pw0 = *(const float4*)(W + (size_t)lr * K + kg);
            pw1 = *(const float4*)(W + (size_t)(lr + 64) * K + kg);
        }
        TILE_COMPUTE2(cur)
        if (has) { STORE_TILE2(nxt) }
        __syncthreads();
    }

    float bs0[8], w2l[8];
    *(float4*)(&bs0[0]) = *(const float4*)(bias + tx * 8);
    *(float4*)(&bs0[4]) = *(const float4*)(bias + tx * 8 + 4);
    *(float4*)(&w2l[0]) = *(const float4*)(w2 + tx * 8);
    *(float4*)(&w2l[4]) = *(const float4*)(w2 + tx * 8 + 4);

#pragma unroll
    for (int ii = 0; ii < 4; ii++) {
        float vr0[8], vr1[8];
#pragma unroll
        for (int j = 0; j < 8; j++) unpack2(acc2[ii][j], vr0[j], vr1[j]);
#pragma unroll
        for (int h = 0; h < 2; h++) {
            float* vv = h ? vr1 : vr0;
            float p = 0.f;
#pragma unroll
            for (int j = 0; j < 8; j++)
                p += tanhf(vv[j] + bs0[j]) * w2l[j];
            // reduce across the 16 tx lanes (xor<16 stays inside half-warp)
#pragma unroll
            for (int off = 8; off; off >>= 1)
                p += __shfl_xor_sync(0xffffffffu, p, off);
            int m = bm + ty * 8 + 2 * ii + h;
            if (tx == 0 && m < M) score[m] = p;
        }
    }
}

// ---------------- fused dual-LSTM step kernel (FFMA2, pack-free) ----------------
__device__ __forceinline__ float sigf(float x) { return 1.f / (1.f + expf(-x)); }

__global__ __launch_bounds__(256, 2) void lstm_step2_kernel(
    const float* __restrict__ Xv, const float* __restrict__ Xs, int ldx,
    const float* __restrict__ Hv, const float* __restrict__ Hs,
    const float* __restrict__ Wcv, const float* __restrict__ Wcs,
    const float* __restrict__ bcv, const float* __restrict__ bcs,
    float* __restrict__ Cv, float* __restrict__ Cs,
    float* __restrict__ Hvo, float* __restrict__ Hso)
{
    __shared__ float As[2][16][128];
    __shared__ float Ws2[2][16][256];

    const int sel = blockIdx.x >> 1;
    const float* X   = sel ? Xs  : Xv;
    const float* Hin = sel ? Hs  : Hv;
    const float* Wc  = sel ? Wcs : Wcv;
    const float* bc  = sel ? bcs : bcv;
    float* Cst  = sel ? Cs  : Cv;
    float* Hout = sel ? Hso : Hvo;

    const int M = CN;
    const int bm = blockIdx.y * 128;
    const int bn = (blockIdx.x & 1) * 128;
    const int tid = threadIdx.x;
    const int lr = tid >> 2;
    const int lk = (tid & 3) << 2;
    const int ty = tid >> 4, tx = tid & 15;

    ull acc2[4][8];
#pragma unroll
    for (int ii = 0; ii < 4; ii++)
#pragma unroll
        for (int j = 0; j < 8; j++) acc2[ii][j] = 0ull;

    int r0 = bm + lr;      r0 = r0 < M ? r0 : (M - 1);
    int r1 = bm + lr + 64; r1 = r1 < M ? r1 : (M - 1);

    float4 pa0, pa1, pw0, pw1;
    {
        int kg = lk;
        pa0 = (kg < 64) ? *(const float4*)(X + (size_t)r0 * ldx + kg)
                        : *(const float4*)(Hin + (size_t)r0 * 64 + (kg - 64));
        pa1 = (kg < 64) ? *(const float4*)(X + (size_t)r1 * ldx + kg)
                        : *(const float4*)(Hin + (size_t)r1 * 64 + (kg - 64));
        pw0 = *(const float4*)(Wc + (size_t)(bn + lr) * 128 + kg);
        pw1 = *(const float4*)(Wc + (size_t)(bn + lr + 64) * 128 + kg);
    }
    STORE_TILE2(0)
    __syncthreads();

#pragma unroll
    for (int t = 0; t < 8; t++) {
        const int cur = t & 1, nxt = cur ^ 1;
        const bool has = t < 7;
        if (has) {
            int kg = ((t + 1) << 4) + lk;
            pa0 = (kg < 64) ? *(const float4*)(X + (size_t)r0 * ldx + kg)
                            : *(const float4*)(Hin + (size_t)r0 * 64 + (kg - 64));
            pa1 = (kg < 64) ? *(const float4*)(X + (size_t)r1 * ldx + kg)
                            : *(const float4*)(Hin + (size_t)r1 * 64 + (kg - 64));
            pw0 = *(const float4*)(Wc + (size_t)(bn + lr) * 128 + kg);
            pw1 = *(const float4*)(Wc + (size_t)(bn + lr + 64) * 128 + kg);
        }
        TILE_COMPUTE2(cur)
        if (has) { STORE_TILE2(nxt) }
        __syncthreads();
    }

    // epilogue: thread cols = 2 complete [i,f,g,o] quadruples -> units u0,u0+1
    const int colbase = bn + tx * 8;
    const int u0 = colbase >> 2;
    float bb[8];
    *(float4*)(&bb[0]) = *(const float4*)(bc + colbase);
    *(float4*)(&bb[4]) = *(const float4*)(bc + colbase + 4);

#pragma unroll
    for (int ii = 0; ii < 4; ii++) {
        float vr0[8], vr1[8];
#pragma unroll
        for (int j = 0; j < 8; j++) unpack2(acc2[ii][j], vr0[j], vr1[j]);
#pragma unroll
        for (int h = 0; h < 2; h++) {
            int m = bm + ty * 8 + 2 * ii + h;
            if (m >= M) continue;
            float* g = h ? vr1 : vr0;
            float2 cold = *(float2*)(Cst + (size_t)m * 64 + u0);
            float c0 = sigf(g[1] + bb[1]) * cold.x + sigf(g[0] + bb[0]) * tanhf(g[2] + bb[2]);
            float c1 = sigf(g[5] + bb[5]) * cold.y + sigf(g[4] + bb[4]) * tanhf(g[6] + bb[6]);
            float2 cn = make_float2(c0, c1);
            float2 hn = make_float2(sigf(g[3] + bb[3]) * tanhf(c0),
                                    sigf(g[7] + bb[7]) * tanhf(c1));
            *(float2*)(Cst + (size_t)m * 64 + u0) = cn;
            *(float2*)(Hout + (size_t)m * 64 + u0) = hn;
        }
    }
}

// ---------------- small kernels ----------------
__global__ void zero_kernel(float* p, size_t n)
{
    size_t i = (size_t)blockIdx.x * blockDim.x + threadIdx.x;
    size_t stride = (size_t)gridDim.x * blockDim.x;
    for (; i < n; i += stride) p[i] = 0.f;
}

// build interleaved LSTM weights: out row 4u+g <- orig row g*64+u, K = [x|h]
__global__ void prep_kernel(const float* __restrict__ Wih_v, const float* __restrict__ Whh_v,
                            const float* __restrict__ bih_v, const float* __restrict__ bhh_v,
                            const float* __restrict__ Wih_s, const float* __restrict__ Whh_s,
                            const float* __restrict__ bih_s, const float* __restrict__ bhh_s,
                            float* __restrict__ S)
{
    int idx = blockIdx.x * blockDim.x + threadIdx.x;
    if (idx < 256 * 128) {
        int o = idx >> 7, k = idx & 127;
        int u = o >> 2, g = o & 3;
        int orow = g * 64 + u;
        S[OFF_WCV + idx] = (k < 64) ? Wih_v[orow * 64 + k] : Whh_v[orow * 64 + (k - 64)];
        S[OFF_WCS + idx] = (k < 64) ? Wih_s[orow * 64 + k] : Whh_s[orow * 64 + (k - 64)];
        if (idx < 256) {
            int uu = idx >> 2, gg = idx & 3;
            int ob = gg * 64 + uu;
            S[OFF_BCV + idx] = bih_v[ob] + bhh_v[ob];
            S[OFF_BCS + idx] = bih_s[ob] + bhh_s[ob];
        }
    }
}

__global__ void copy_xp_kernel(float* __restrict__ S)
{
    size_t idx = (size_t)blockIdx.x * blockDim.x + threadIdx.x;
    if (idx >= (size_t)CN * 128) return;
    size_t n = idx >> 7;
    int j = (int)(idx & 127);
    S[OFF_XCAT + n * 512 + 384 + j] = S[OFF_XCAT + n * 512 + 128 + j];
}

__global__ void deg_kernel(const int* __restrict__ dst, float* __restrict__ deg)
{
    int e = blockIdx.x * blockDim.x + threadIdx.x;
    if (e < CE) atomicAdd(&deg[dst[e]], 1.0f);
}

__global__ void dinv_kernel(float* __restrict__ S)
{
    int n = blockIdx.x * blockDim.x + threadIdx.x;
    if (n < CN) S[OFF_DINV + n] = rsqrtf(fmaxf(S[OFF_DEG + n], 1.0f));
}

// single-block exclusive scan of (int)deg -> off[0..CN], cur = off
__global__ __launch_bounds__(1024) void scan_kernel(const float* __restrict__ deg,
                                                    int* __restrict__ off,
                                                    int* __restrict__ cur)
{
    __shared__ int part[1024];
    const int tid = threadIdx.x;
    const int chunk = (CN + 1023) / 1024;
    const int start = tid * chunk;
    const int end = min(start + chunk, CN);
    int s = 0;
    for (int i = start; i < end; i++) s += (int)deg[i];
    part[tid] = s;
    __syncthreads();
    for (int d = 1; d < 1024; d <<= 1) {
        int v = (tid >= d) ? part[tid - d] : 0;
        __syncthreads();
        part[tid] += v;
        __syncthreads();
    }
    int pre = (tid == 0) ? 0 : part[tid - 1];
    for (int i = start; i < end; i++) {
        off[i] = pre;
        cur[i] = pre;
        pre += (int)deg[i];
    }
    if (tid == 1023) off[CN] = pre;
}

// fill CSR: for each edge, place src into the dst's segment
__global__ void fill_kernel(const int* __restrict__ src, const int* __restrict__ dst,
                            int* __restrict__ cur, int* __restrict__ csr)
{
    int e = blockIdx.x * blockDim.x + threadIdx.x;
    if (e < CE) {
        int d = dst[e];
        int pos = atomicAdd(&cur[d], 1);
        csr[pos] = src[e];
    }
}

// gather propagation: out[n] = pin[n] - dinv[n] * sum_{s in N(n)} pin[s]*dinv[s]
__global__ __launch_bounds__(256) void prop_kernel(
    const float* __restrict__ pin, int ldin,
    const int* __restrict__ csr, const int* __restrict__ off,
    const float* __restrict__ dinv, float* __restrict__ outp)
{
    const int n = blockIdx.x * 8 + (threadIdx.x >> 5);
    if (n >= CN) return;
    const int lane = threadIdx.x & 31;
    const int col = lane * 4;
    float4 acc = make_float4(0.f, 0.f, 0.f, 0.f);
    const int s0 = off[n], s1 = off[n + 1];
    for (int e = s0; e < s1; e++) {
        int sn = csr[e];
        float ds = __ldg(&dinv[sn]);
        float4 v = *(const float4*)(pin + (size_t)sn * ldin + col);
        acc.x += v.x * ds; acc.y += v.y * ds; acc.z += v.z * ds; acc.w += v.w * ds;
    }
    const float dn = dinv[n];
    float4 pv = *(const float4*)(pin + (size_t)n * ldin + col);
    float4 o = make_float4(pv.x - acc.x * dn, pv.y - acc.y * dn,
                           pv.z - acc.z * dn, pv.w - acc.w * dn);
    *(float4*)(outp + (size_t)n * 128 + col) = o;
}

// second propagation fused with filter construction
__global__ __launch_bounds__(256) void prop2F_kernel(
    const float* __restrict__ p1,
    const float* __restrict__ p0, int ld0,
    const int* __restrict__ csr, const int* __restrict__ off,
    const float* __restrict__ dinv, float* __restrict__ F)
{
    const int n = blockIdx.x * 8 + (threadIdx.x >> 5);
    if (n >= CN) return;
    const int lane = threadIdx.x & 31;
    const int col = lane * 4;
    float4 acc = make_float4(0.f, 0.f, 0.f, 0.f);
    const int s0 = off[n], s1 = off[n + 1];
    for (int e = s0; e < s1; e++) {
        int sn = csr[e];
        float ds = __ldg(&dinv[sn]);
        float4 v = *(const float4*)(p1 + (size_t)sn * 128 + col);
        acc.x += v.x * ds; acc.y += v.y * ds; acc.z += v.z * ds; acc.w += v.w * ds;
    }
    const float dn = dinv[n];
    float4 b = *(const float4*)(p1 + (size_t)n * 128 + col);
    float4 a = *(const float4*)(p0 + (size_t)n * ld0 + col);
    float4 c = make_float4(b.x - acc.x * dn, b.y - acc.y * dn,
                           b.z - acc.z * dn, b.w - acc.w * dn);
    float* Fb = F + (size_t)n * 640 + col;
    float4 f0 = make_float4(0.8f * a.x - 0.5f * b.x, 0.8f * a.y - 0.5f * b.y,
                            0.8f * a.z - 0.5f * b.z, 0.8f * a.w - 0.5f * b.w);
    float4 f1 = make_float4(3.0f * a.x - 3.0f * b.x + 0.75f * c.x,
                            3.0f * a.y - 3.0f * b.y + 0.75f * c.y,
                            3.0f * a.z - 3.0f * b.z + 0.75f * c.z,
                            3.0f * a.w - 3.0f * b.w + 0.75f * c.w);
    float4 f2 = make_float4(3.0f * b.x - 1.5f * c.x, 3.0f * b.y - 1.5f * c.y,
                            3.0f * b.z - 1.5f * c.z, 3.0f * b.w - 1.5f * c.w);
    float4 f3 = make_float4(0.75f * c.x, 0.75f * c.y, 0.75f * c.z, 0.75f * c.w);
    float4 f4 = make_float4(-0.2f * a.x + 0.5f * b.x, -0.2f * a.y + 0.5f * b.y,
                            -0.2f * a.z + 0.5f * b.z, -0.2f * a.w + 0.5f * b.w);
    *(float4*)(Fb)       = f0;
    *(float4*)(Fb + 128) = f1;
    *(float4*)(Fb + 256) = f2;
    *(float4*)(Fb + 384) = f3;
    *(float4*)(Fb + 512) = f4;
}

// softmax over 5 per-node scores; res = sum_f soft_f * F_f
__global__ void attn_res_kernel(const float* __restrict__ score, const float* __restrict__ F,
                                float* __restrict__ res)
{
    size_t gid = (size_t)blockIdx.x * blockDim.x + threadIdx.x;
    int n = (int)(gid >> 5);
    int lane = (int)(gid & 31);
    if (n >= CN) return;
    float sc[5];
#pragma unroll
    for (int f = 0; f < 5; f++) sc[f] = score[(size_t)n * 5 + f];
    float mx = sc[0];
#pragma unroll
    for (int f = 1; f < 5; f++) mx = fmaxf(mx, sc[f]);
    float e[5], s = 0.f;
#pragma unroll
    for (int f = 0; f < 5; f++) { e[f] = expf(sc[f] - mx); s += e[f]; }
    float inv = 1.f / s;
    const float* Fb = F + (size_t)n * 640;
    const int col = lane * 4;
    float4 r = make_float4(0.f, 0.f, 0.f, 0.f);
#pragma unroll
    for (int f = 0; f < 5; f++) {
        float4 v = *(const float4*)(Fb + f * 128 + col);
        float w = e[f];
        r.x += w * v.x; r.y += w * v.y; r.z += w * v.z; r.w += w * v.w;
    }
    r.x *= inv; r.y *= inv; r.z *= inv; r.w *= inv;
    *(float4*)(res + (size_t)n * 128 + col) = r;
}

// out[n, c] = big[n, :] . W6[c, :] + b6[c], warp per node
__global__ void final_kernel(const float* __restrict__ big, const float* __restrict__ W6,
                             const float* __restrict__ b6, float* __restrict__ out)
{
    size_t gid = (size_t)blockIdx.x * blockDim.x + threadIdx.x;
    int n = (int)(gid >> 5);
    int lane = (int)(gid & 31);
    if (n >= CN) return;
    const float* row = big + (size_t)n * 768;
#pragma unroll
    for (int c = 0; c < 2; c++) {
        float a = 0.f;
        for (int j = lane; j < 768; j += 32) a += row[j] * W6[c * 768 + j];
#pragma unroll
        for (int off = 16; off; off >>= 1) a += __shfl_xor_sync(0xffffffffu, a, off);
        if (lane == 0) out[(size_t)n * 2 + c] = a + b6[c];
    }
}

// ---------------- orchestration ----------------
extern "C" void kernel_launch(void* const* d_in, const int* in_sizes, int n_in,
                              void* d_out, int out_size)
{
    const float* voc    = (const float*)d_in[0];
    const float* sms    = (const float*)d_in[1];
    const float* pers   = (const float*)d_in[2];
    const float* Wih_v  = (const float*)d_in[3];
    const float* Whh_v  = (const float*)d_in[4];
    const float* bih_v  = (const float*)d_in[5];
    const float* bhh_v  = (const float*)d_in[6];
    const float* Wih_s  = (const float*)d_in[7];
    const float* Whh_s  = (const float*)d_in[8];
    const float* bih_s  = (const float*)d_in[9];
    const float* bhh_s  = (const float*)d_in[10];
    const float* W_lin  = (const float*)d_in[11];
    const float* b_lin  = (const float*)d_in[12];
    const float* W_lin1 = (const float*)d_in[13];
    const float* b_lin1 = (const float*)d_in[14];
    const float* W_pers = (const float*)d_in[15];
    const float* b_pers = (const float*)d_in[16];
    const float* W_lin2 = (const float*)d_in[17];
    const float* b_lin2 = (const float*)d_in[18];
    const float* W_lin3 = (const float*)d_in[19];
    const float* b_lin3 = (const float*)d_in[20];
    const float* W_lin4 = (const float*)d_in[21];
    const float* b_lin4 = (const float*)d_in[22];
    const float* W_lin5 = (const float*)d_in[23];
    const float* b_lin5 = (const float*)d_in[24];
    const float* Wf1    = (const float*)d_in[25];
    const float* bf1    = (const float*)d_in[26];
    const float* Wf2    = (const float*)d_in[27];
    const float* W_lin6 = (const float*)d_in[28];
    const float* b_lin6 = (const float*)d_in[29];
    const int*   src    = (const int*)d_in[30];
    const int*   dst    = (const int*)d_in[31];
    float* out = (float*)d_out;

    float* S = nullptr;
    cudaGetSymbolAddress((void**)&S, g_scratch);
    int* csr = nullptr; cudaGetSymbolAddress((void**)&csr, g_csr);
    int* offp = nullptr; cudaGetSymbolAddress((void**)&offp, g_off);
    int* curp = nullptr; cudaGetSymbolAddress((void**)&curp, g_cur);

    // prep: interleaved LSTM weights/biases, zero states (HV0,HV1,HS0,HS1,CV,CS)
    prep_kernel<<<(256 * 128 + 255) / 256, 256>>>(Wih_v, Whh_v, bih_v, bhh_v,
                                                  Wih_s, Whh_s, bih_s, bhh_s, S);
    zero_kernel<<<4096, 256>>>(S + OFF_HV0, (size_t)6 * CN * 64);

    // ---- LSTMs: 16 steps, both LSTMs per launch, fused GEMM+cell ----
    dim3 lgrid(4, (CN + 127) / 128);
    for (int t = 0; t < CT; t++) {
        const float* hv_in  = S + ((t & 1) ? OFF_HV1 : OFF_HV0);
        float*       hv_out = S + ((t & 1) ? OFF_HV0 : OFF_HV1);
        const float* hs_in  = S + ((t & 1) ? OFF_HS1 : OFF_HS0);
        float*       hs_out = S + ((t & 1) ? OFF_HS0 : OFF_HS1);
        lstm_step2_kernel<<<lgrid, 256>>>(voc + (size_t)t * 64, sms + (size_t)t * 64, CT * 64,
                                          hv_in, hs_in,
                                          S + OFF_WCV, S + OFF_WCS,
                                          S + OFF_BCV, S + OFF_BCS,
                                          S + OFF_CV, S + OFF_CS,
                                          hv_out, hs_out);
    }
    // final h is in HV0 / HS0 (16 steps, even)

    // ---- projections ----
    gemm(S + OFF_HV0, 64, 64, S + OFF_HV0, 64, W_lin, b_lin,
         S + OFF_XCAT + 0, 512, CN, 128, 64, 1);
    gemm(S + OFF_HS0, 64, 64, S + OFF_HS0, 64, W_lin1, b_lin1,
         S + OFF_XCAT + 256, 512, CN, 128, 64, 1);
    gemm(pers, 32, 32, pers, 32, W_pers, b_pers,
         S + OFF_XCAT + 128, 512, CN, 128, 32, 1);
    copy_xp_kernel<<<((size_t)CN * 128 + 255) / 256, 256>>>(S);

    gemm(S + OFF_XCAT, 512, 256, S + OFF_XCAT, 512, W_lin2, b_lin2,
         S + OFF_BIG + 384, 768, CN, 128, 256, 1);
    gemm(S + OFF_XCAT + 256, 512, 256, S + OFF_XCAT + 256, 512, W_lin3, b_lin3,
         S + OFF_BIG + 512, 768, CN, 128, 256, 1);
    gemm(S + OFF_XCAT, 512, 512, S + OFF_XCAT, 512, W_lin4, b_lin4,
         S + OFF_BIG + 640, 768, CN, 128, 512, 1);

    // ---- relation graphs (CSR gather-based propagation) ----
    const int pgrid = (CN + 7) / 8;
    for (int r = 0; r < CR; r++) {
        const int* sr = src + (size_t)r * CE;
        const int* dr = dst + (size_t)r * CE;
        const float* p0 = S + OFF_BIG + 384 + 128 * r;  // lda 768

        zero_kernel<<<256, 256>>>(S + OFF_DEG, (size_t)CN);
        deg_kernel<<<(CE + 255) / 256, 256>>>(dr, S + OFF_DEG);
        dinv_kernel<<<(CN + 255) / 256, 256>>>(S);
        scan_kernel<<<1, 1024>>>(S + OFF_DEG, offp, curp);
        fill_kernel<<<(CE + 255) / 256, 256>>>(sr, dr, curp, csr);

        prop_kernel<<<pgrid, 256>>>(p0, 768, csr, offp, S + OFF_DINV, S + OFF_P1);
        prop2F_kernel<<<pgrid, 256>>>(S + OFF_P1, p0, 768, csr, offp,
                                      S + OFF_DINV, S + OFF_F);

        // scores = w2 . tanh(F @ Wf1^T + bf1) fused (Y never materialized)
        {
            dim3 sgrid(1, (CN * 5 + 127) / 128);
            sgemm_score_kernel<<<sgrid, 256>>>(S + OFF_F, 128,
                                               Wf1 + (size_t)r * 128 * 128,
                                               bf1 + (size_t)r * 128,
                                               Wf2 + (size_t)r * 128,
                                               S + OFF_SC, CN * 5);
        }

        attn_res_kernel<<<((size_t)CN * 32 + 255) / 256, 256>>>(S + OFF_SC, S + OFF_F,
                                                                S + OFF_RES);

        // hall_r = act(res @ W_lin5[r]^T + b_lin5[r]) -> big cols [128r, 128r+128)
        gemm(S + OFF_RES, 128, 128, S + OFF_RES, 128,
             W_lin5 + (size_t)r * 128 * 128, b_lin5 + (size_t)r * 128,
             S + OFF_BIG + 128 * r, 768, CN, 128, 128, 1);
    }

    // ---- final head ----
    final_kernel<<<((size_t)CN * 32 + 255) / 256, 256>>>(S + OFF_BIG, W_lin6, b_lin6, out);
}

// round 7
// speedup vs baseline: 2.3787x; 2.3787x over previous
#include <cuda_runtime.h>
#include <math.h>
#include <stdint.h>

// Problem constants
#define CN 50000
#define CE 800000
#define CR 3
#define CT 16

typedef unsigned long long ull;

__device__ __forceinline__ ull pack2(float lo, float hi) {
    ull r; asm("mov.b64 %0, {%1,%2};" : "=l"(r) : "f"(lo), "f"(hi)); return r;
}
__device__ __forceinline__ ull fma2(ull a, ull b, ull c) {
    ull d; asm("fma.rn.f32x2 %0, %1, %2, %3;" : "=l"(d) : "l"(a), "l"(b), "l"(c)); return d;
}
__device__ __forceinline__ void unpack2(ull v, float& lo, float& hi) {
    asm("mov.b64 {%0,%1}, %2;" : "=f"(lo), "=f"(hi) : "l"(v));
}

// ---------------- scratch layout (floats) ----------------
constexpr size_t SZ_WCAT = 256 * 128;
constexpr size_t OFF_WCV = 0;
constexpr size_t OFF_WCS = OFF_WCV + SZ_WCAT;
constexpr size_t OFF_BCV = OFF_WCS + SZ_WCAT;
constexpr size_t OFF_BCS = OFF_BCV + 256;
constexpr size_t OFF_HV0 = OFF_BCS + 256;                 // N*64 each
constexpr size_t OFF_HV1 = OFF_HV0 + (size_t)CN * 64;
constexpr size_t OFF_HS0 = OFF_HV1 + (size_t)CN * 64;
constexpr size_t OFF_HS1 = OFF_HS0 + (size_t)CN * 64;
constexpr size_t OFF_CV  = OFF_HS1 + (size_t)CN * 64;
constexpr size_t OFF_CS  = OFF_CV + (size_t)CN * 64;
constexpr size_t OFF_XCAT= OFF_CS + (size_t)CN * 64;      // [xv|xp|xs|xp] N*512
constexpr size_t OFF_BIG = OFF_XCAT + (size_t)CN * 512;   // [hall0..2, xin0..2] N*768
constexpr size_t OFF_P1  = OFF_BIG + (size_t)CN * 768;    // N*128
constexpr size_t OFF_DEG = OFF_P1 + (size_t)CN * 128;     // N
constexpr size_t OFF_DINV= OFF_DEG + CN;                  // N
constexpr size_t OFF_F   = OFF_DINV + CN;                 // N*5*128
constexpr size_t OFF_SC  = OFF_F + (size_t)CN * 640;      // scores N*5
constexpr size_t OFF_RES = OFF_SC + (size_t)CN * 5 + 64;  // N*128
constexpr size_t SCRATCH_TOTAL = OFF_RES + (size_t)CN * 128;

__device__ float g_scratch[SCRATCH_TOTAL];
__device__ int g_csr[CE];
__device__ int g_off[CN + 1];
__device__ int g_cur[CN];

// =====================================================================
// FFMA2 GEMM core (PROVEN R5 shape): 128x128 tile, BK=16, double-buffered,
// 256 threads, 8x8/thread; acc2[i][jj] packs output cols (2jj, 2jj+1).
// =====================================================================
#define TILE_COMPUTE(cur)                                                      \
    _Pragma("unroll")                                                          \
    for (int kk = 0; kk < 16; kk++) {                                          \
        float a[8]; ull b2[4];                                                 \
        *(float4*)(&a[0]) = *(const float4*)(&As[cur][kk][ty * 8]);            \
        *(float4*)(&a[4]) = *(const float4*)(&As[cur][kk][ty * 8 + 4]);        \
        {                                                                      \
            const ulonglong2* wp = (const ulonglong2*)(&Ws[cur][kk][tx * 8]);  \
            ulonglong2 w0 = wp[0]; ulonglong2 w1 = wp[1];                      \
            b2[0] = w0.x; b2[1] = w0.y; b2[2] = w1.x; b2[3] = w1.y;            \
        }                                                                      \
        _Pragma("unroll")                                                      \
        for (int i = 0; i < 8; i++) {                                          \
            ull ai = pack2(a[i], a[i]);                                        \
            _Pragma("unroll")                                                  \
            for (int jj = 0; jj < 4; jj++)                                     \
                acc2[i][jj] = fma2(ai, b2[jj], acc2[i][jj]);                   \
        }                                                                      \
    }

#define STORE_TILE(buf)                                                                         \
    As[buf][lk+0][lr] = pa0.x; As[buf][lk+1][lr] = pa0.y;                                       \
    As[buf][lk+2][lr] = pa0.z; As[buf][lk+3][lr] = pa0.w;                                       \
    As[buf][lk+0][lr+64] = pa1.x; As[buf][lk+1][lr+64] = pa1.y;                                 \
    As[buf][lk+2][lr+64] = pa1.z; As[buf][lk+3][lr+64] = pa1.w;                                 \
    Ws[buf][lk+0][lr] = pw0.x; Ws[buf][lk+1][lr] = pw0.y;                                       \
    Ws[buf][lk+2][lr] = pw0.z; Ws[buf][lk+3][lr] = pw0.w;                                       \
    Ws[buf][lk+0][lr+64] = pw1.x; Ws[buf][lk+1][lr+64] = pw1.y;                                 \
    Ws[buf][lk+2][lr+64] = pw1.z; Ws[buf][lk+3][lr+64] = pw1.w;

// ---------------- generic SGEMM:  C = act(A @ W^T + bias) ----------------
__global__ __launch_bounds__(256) void sgemm_kernel(
    const float* __restrict__ A, int lda, int K1,
    const float* __restrict__ A2, int lda2,
    const float* __restrict__ W,
    const float* __restrict__ bias,
    float* __restrict__ C, int ldc,
    int M, int K, int act)
{
    __shared__ float As[2][16][128];
    __shared__ float Ws[2][16][128];

    const int bm = blockIdx.y * 128;
    const int bn = blockIdx.x * 128;
    const int tid = threadIdx.x;
    const int lr = tid >> 2;
    const int lk = (tid & 3) << 2;
    const int ty = tid >> 4, tx = tid & 15;

    ull acc2[8][4];
#pragma unroll
    for (int i = 0; i < 8; i++)
#pragma unroll
        for (int jj = 0; jj < 4; jj++) acc2[i][jj] = 0ull;

    int r0 = bm + lr;      r0 = r0 < M ? r0 : (M - 1);
    int r1 = bm + lr + 64; r1 = r1 < M ? r1 : (M - 1);

    float4 pa0, pa1, pw0, pw1;
    {
        int kg = lk;
        pa0 = (kg < K1) ? *(const float4*)(A + (size_t)r0 * lda + kg)
                        : *(const float4*)(A2 + (size_t)r0 * lda2 + (kg - K1));
        pa1 = (kg < K1) ? *(const float4*)(A + (size_t)r1 * lda + kg)
                        : *(const float4*)(A2 + (size_t)r1 * lda2 + (kg - K1));
        pw0 = *(const float4*)(W + (size_t)(bn + lr) * K + kg);
        pw1 = *(const float4*)(W + (size_t)(bn + lr + 64) * K + kg);
    }
    STORE_TILE(0)
    __syncthreads();

    const int ntiles = K >> 4;
    for (int t = 0; t < ntiles; t++) {
        const int cur = t & 1, nxt = cur ^ 1;
        const bool has = (t + 1) < ntiles;
        if (has) {
            int kg = ((t + 1) << 4) + lk;
            pa0 = (kg < K1) ? *(const float4*)(A + (size_t)r0 * lda + kg)
                            : *(const float4*)(A2 + (size_t)r0 * lda2 + (kg - K1));
            pa1 = (kg < K1) ? *(const float4*)(A + (size_t)r1 * lda + kg)
                            : *(const float4*)(A2 + (size_t)r1 * lda2 + (kg - K1));
            pw0 = *(const float4*)(W + (size_t)(bn + lr) * K + kg);
            pw1 = *(const float4*)(W + (size_t)(bn + lr + 64) * K + kg);
        }
        TILE_COMPUTE(cur)
        if (has) { STORE_TILE(nxt) }
        __syncthreads();
    }

    float bs0[8];
    *(float4*)(&bs0[0]) = *(const float4*)(bias + bn + tx * 8);
    *(float4*)(&bs0[4]) = *(const float4*)(bias + bn + tx * 8 + 4);

#pragma unroll
    for (int i = 0; i < 8; i++) {
        int m = bm + ty * 8 + i;
        if (m >= M) continue;
        float v[8];
#pragma unroll
        for (int jj = 0; jj < 4; jj++) {
            float lo, hi; unpack2(acc2[i][jj], lo, hi);
            v[2 * jj] = lo; v[2 * jj + 1] = hi;
        }
#pragma unroll
        for (int j = 0; j < 8; j++) {
            float x = v[j] + bs0[j];
            if (act == 1)      x = x > 0.f ? x : 0.01f * x;
            else if (act == 2) x = tanhf(x);
            v[j] = x;
        }
        float* cp = C + (size_t)m * ldc + bn + tx * 8;
        *(float4*)(cp)     = *(float4*)(&v[0]);
        *(float4*)(cp + 4) = *(float4*)(&v[4]);
    }
}

static inline void gemm(const float* A, int lda, int K1,
                        const float* A2, int lda2,
                        const float* W, const float* bias,
                        float* C, int ldc, int M, int O, int K, int act)
{
    dim3 grid(O / 128, (M + 127) / 128);
    sgemm_kernel<<<grid, 256>>>(A, lda, K1, A2, lda2, W, bias, C, ldc, M, K, act);
}

// ---------------- score GEMM: score[m] = w2 . tanh(A[m] @ W^T + bias) ----------------
// O = 128 exactly (one column tile). Y never materialized.
__global__ __launch_bounds__(256) void sgemm_score_kernel(
    const float* __restrict__ A, int lda,
    const float* __restrict__ W,
    const float* __restrict__ bias,
    const float* __restrict__ w2,
    float* __restrict__ score,
    int M)
{
    __shared__ float As[2][16][128];
    __shared__ float Ws[2][16][128];

    const int bm = blockIdx.y * 128;
    const int tid = threadIdx.x;
    const int lr = tid >> 2;
    const int lk = (tid & 3) << 2;
    const int ty = tid >> 4, tx = tid & 15;
    const int K = 128;

    ull acc2[8][4];
#pragma unroll
    for (int i = 0; i < 8; i++)
#pragma unroll
        for (int jj = 0; jj < 4; jj++) acc2[i][jj] = 0ull;

    int r0 = bm + lr;      r0 = r0 < M ? r0 : (M - 1);
    int r1 = bm + lr + 64; r1 = r1 < M ? r1 : (M - 1);

    float4 pa0, pa1, pw0, pw1;
    {
        int kg = lk;
        pa0 = *(const float4*)(A + (size_t)r0 * lda + kg);
        pa1 = *(const float4*)(A + (size_t)r1 * lda + kg);
        pw0 = *(const float4*)(W + (size_t)lr * K + kg);
        pw1 = *(const float4*)(W + (size_t)(lr + 64) * K + kg);
    }
    STORE_TILE(0)
    __syncthreads();

#pragma unroll
    for (int t = 0; t < 8; t++) {
        const int cur = t & 1, nxt = cur ^ 1;
        const bool has = t < 7;
        if (has) {
            int kg = ((t + 1) << 4) + lk;
            pa0 = *(const float4*)(A + (size_t)r0 * lda + kg);
            pa1 = *(const float4*)(A + (size_t)r1 * lda + kg);
            pw0 = *(const float4*)(W + (size_t)lr * K + kg);
            pw1 = *(const float4*)(W + (size_t)(lr + 64) * K + kg);
        }
        TILE_COMPUTE(cur)
        if (has) { STORE_TILE(nxt) }
        __syncthreads();
    }

    float bs0[8], w2l[8];
    *(float4*)(&bs0[0]) = *(const float4*)(bias + tx * 8);
    *(float4*)(&bs0[4]) = *(const float4*)(bias + tx * 8 + 4);
    *(float4*)(&w2l[0]) = *(const float4*)(w2 + tx * 8);
    *(float4*)(&w2l[4]) = *(const float4*)(w2 + tx * 8 + 4);

#pragma unroll
    for (int i = 0; i < 8; i++) {
        float v[8];
#pragma unroll
        for (int jj = 0; jj < 4; jj++) {
            float lo, hi; unpack2(acc2[i][jj], lo, hi);
            v[2 * jj] = lo; v[2 * jj + 1] = hi;
        }
        float p = 0.f;
#pragma unroll
        for (int j = 0; j < 8; j++)
            p += tanhf(v[j] + bs0[j]) * w2l[j];
        // reduce across the 16 tx lanes (xor<16 stays within half-warp)
#pragma unroll
        for (int off = 8; off; off >>= 1)
            p += __shfl_xor_sync(0xffffffffu, p, off);
        int m = bm + ty * 8 + i;
        if (tx == 0 && m < M) score[m] = p;
    }
}

// ---------------- fused dual-LSTM step kernel (FFMA2, R5-proven) ----------------
__device__ __forceinline__ float sigf(float x) { return 1.f / (1.f + expf(-x)); }

__global__ __launch_bounds__(256) void lstm_step2_kernel(
    const float* __restrict__ Xv, const float* __restrict__ Xs, int ldx,
    const float* __restrict__ Hv, const float* __restrict__ Hs,
    const float* __restrict__ Wcv, const float* __restrict__ Wcs,
    const float* __restrict__ bcv, const float* __restrict__ bcs,
    float* __restrict__ Cv, float* __restrict__ Cs,
    float* __restrict__ Hvo, float* __restrict__ Hso)
{
    __shared__ float As[2][16][128];
    __shared__ float Ws[2][16][128];

    const int sel = blockIdx.x >> 1;
    const float* X   = sel ? Xs  : Xv;
    const float* Hin = sel ? Hs  : Hv;
    const float* Wc  = sel ? Wcs : Wcv;
    const float* bc  = sel ? bcs : bcv;
    float* Cst  = sel ? Cs  : Cv;
    float* Hout = sel ? Hso : Hvo;

    const int M = CN;
    const int bm = blockIdx.y * 128;
    const int bn = (blockIdx.x & 1) * 128;
    const int tid = threadIdx.x;
    const int lr = tid >> 2;
    const int lk = (tid & 3) << 2;
    const int ty = tid >> 4, tx = tid & 15;

    ull acc2[8][4];
#pragma unroll
    for (int i = 0; i < 8; i++)
#pragma unroll
        for (int jj = 0; jj < 4; jj++) acc2[i][jj] = 0ull;

    int r0 = bm + lr;      r0 = r0 < M ? r0 : (M - 1);
    int r1 = bm + lr + 64; r1 = r1 < M ? r1 : (M - 1);

    float4 pa0, pa1, pw0, pw1;
    {
        int kg = lk;
        pa0 = (kg < 64) ? *(const float4*)(X + (size_t)r0 * ldx + kg)
                        : *(const float4*)(Hin + (size_t)r0 * 64 + (kg - 64));
        pa1 = (kg < 64) ? *(const float4*)(X + (size_t)r1 * ldx + kg)
                        : *(const float4*)(Hin + (size_t)r1 * 64 + (kg - 64));
        pw0 = *(const float4*)(Wc + (size_t)(bn + lr) * 128 + kg);
        pw1 = *(const float4*)(Wc + (size_t)(bn + lr + 64) * 128 + kg);
    }
    STORE_TILE(0)
    __syncthreads();

#pragma unroll
    for (int t = 0; t < 8; t++) {
        const int cur = t & 1, nxt = cur ^ 1;
        const bool has = t < 7;
        if (has) {
            int kg = ((t + 1) << 4) + lk;
            pa0 = (kg < 64) ? *(const float4*)(X + (size_t)r0 * ldx + kg)
                            : *(const float4*)(Hin + (size_t)r0 * 64 + (kg - 64));
            pa1 = (kg < 64) ? *(const float4*)(X + (size_t)r1 * ldx + kg)
                            : *(const float4*)(Hin + (size_t)r1 * 64 + (kg - 64));
            pw0 = *(const float4*)(Wc + (size_t)(bn + lr) * 128 + kg);
            pw1 = *(const float4*)(Wc + (size_t)(bn + lr + 64) * 128 + kg);
        }
        TILE_COMPUTE(cur)
        if (has) { STORE_TILE(nxt) }
        __syncthreads();
    }

    // epilogue: thread cols = 2 complete [i,f,g,o] quadruples -> units u0,u0+1
    const int colbase = bn + tx * 8;
    const int u0 = colbase >> 2;
    float bb[8];
    *(float4*)(&bb[0]) = *(const float4*)(bc + colbase);
    *(float4*)(&bb[4]) = *(const float4*)(bc + colbase + 4);

#pragma unroll
    for (int i = 0; i < 8; i++) {
        int m = bm + ty * 8 + i;
        if (m >= M) continue;
        float g[8];
#pragma unroll
        for (int jj = 0; jj < 4; jj++) {
            float lo, hi; unpack2(acc2[i][jj], lo, hi);
            g[2 * jj] = lo + bb[2 * jj]; g[2 * jj + 1] = hi + bb[2 * jj + 1];
        }
        float2 cold = *(float2*)(Cst + (size_t)m * 64 + u0);
        float c0 = sigf(g[1]) * cold.x + sigf(g[0]) * tanhf(g[2]);
        float c1 = sigf(g[5]) * cold.y + sigf(g[4]) * tanhf(g[6]);
        float2 cn = make_float2(c0, c1);
        float2 hn = make_float2(sigf(g[3]) * tanhf(c0), sigf(g[7]) * tanhf(c1));
        *(float2*)(Cst + (size_t)m * 64 + u0) = cn;
        *(float2*)(Hout + (size_t)m * 64 + u0) = hn;
    }
}

// ---------------- small kernels ----------------
__global__ void zero_kernel(float* p, size_t n)
{
    size_t i = (size_t)blockIdx.x * blockDim.x + threadIdx.x;
    size_t stride = (size_t)gridDim.x * blockDim.x;
    for (; i < n; i += stride) p[i] = 0.f;
}

// build interleaved LSTM weights: out row 4u+g <- orig row g*64+u, K = [x|h]
__global__ void prep_kernel(const float* __restrict__ Wih_v, const float* __restrict__ Whh_v,
                            const float* __restrict__ bih_v, const float* __restrict__ bhh_v,
                            const float* __restrict__ Wih_s, const float* __restrict__ Whh_s,
                            const float* __restrict__ bih_s, const float* __restrict__ bhh_s,
                            float* __restrict__ S)
{
    int idx = blockIdx.x * blockDim.x + threadIdx.x;
    if (idx < 256 * 128) {
        int o = idx >> 7, k = idx & 127;
        int u = o >> 2, g = o & 3;
        int orow = g * 64 + u;
        S[OFF_WCV + idx] = (k < 64) ? Wih_v[orow * 64 + k] : Whh_v[orow * 64 + (k - 64)];
        S[OFF_WCS + idx] = (k < 64) ? Wih_s[orow * 64 + k] : Whh_s[orow * 64 + (k - 64)];
        if (idx < 256) {
            int uu = idx >> 2, gg = idx & 3;
            int ob = gg * 64 + uu;
            S[OFF_BCV + idx] = bih_v[ob] + bhh_v[ob];
            S[OFF_BCS + idx] = bih_s[ob] + bhh_s[ob];
        }
    }
}

__global__ void copy_xp_kernel(float* __restrict__ S)
{
    size_t idx = (size_t)blockIdx.x * blockDim.x + threadIdx.x;
    if (idx >= (size_t)CN * 128) return;
    size_t n = idx >> 7;
    int j = (int)(idx & 127);
    S[OFF_XCAT + n * 512 + 384 + j] = S[OFF_XCAT + n * 512 + 128 + j];
}

__global__ void deg_kernel(const int* __restrict__ dst, float* __restrict__ deg)
{
    int e = blockIdx.x * blockDim.x + threadIdx.x;
    if (e < CE) atomicAdd(&deg[dst[e]], 1.0f);
}

__global__ void dinv_kernel(float* __restrict__ S)
{
    int n = blockIdx.x * blockDim.x + threadIdx.x;
    if (n < CN) S[OFF_DINV + n] = rsqrtf(fmaxf(S[OFF_DEG + n], 1.0f));
}

// single-block exclusive scan of (int)deg -> off[0..CN], cur = off
__global__ __launch_bounds__(1024) void scan_kernel(const float* __restrict__ deg,
                                                    int* __restrict__ off,
                                                    int* __restrict__ cur)
{
    __shared__ int part[1024];
    const int tid = threadIdx.x;
    const int chunk = (CN + 1023) / 1024;
    const int start = tid * chunk;
    const int end = min(start + chunk, CN);
    int s = 0;
    for (int i = start; i < end; i++) s += (int)deg[i];
    part[tid] = s;
    __syncthreads();
    for (int d = 1; d < 1024; d <<= 1) {
        int v = (tid >= d) ? part[tid - d] : 0;
        __syncthreads();
        part[tid] += v;
        __syncthreads();
    }
    int pre = (tid == 0) ? 0 : part[tid - 1];
    for (int i = start; i < end; i++) {
        off[i] = pre;
        cur[i] = pre;
        pre += (int)deg[i];
    }
    if (tid == 1023) off[CN] = pre;
}

// fill CSR: for each edge, place src into the dst's segment
__global__ void fill_kernel(const int* __restrict__ src, const int* __restrict__ dst,
                            int* __restrict__ cur, int* __restrict__ csr)
{
    int e = blockIdx.x * blockDim.x + threadIdx.x;
    if (e < CE) {
        int d = dst[e];
        int pos = atomicAdd(&cur[d], 1);
        csr[pos] = src[e];
    }
}

// gather propagation: out[n] = pin[n] - dinv[n] * sum_{s in N(n)} pin[s]*dinv[s]
__global__ __launch_bounds__(256) void prop_kernel(
    const float* __restrict__ pin, int ldin,
    const int* __restrict__ csr, const int* __restrict__ off,
    const float* __restrict__ dinv, float* __restrict__ outp)
{
    const int n = blockIdx.x * 8 + (threadIdx.x >> 5);
    if (n >= CN) return;
    const int lane = threadIdx.x & 31;
    const int col = lane * 4;
    float4 acc = make_float4(0.f, 0.f, 0.f, 0.f);
    const int s0 = off[n], s1 = off[n + 1];
    for (int e = s0; e < s1; e++) {
        int sn = csr[e];
        float ds = __ldg(&dinv[sn]);
        float4 v = *(const float4*)(pin + (size_t)sn * ldin + col);
        acc.x += v.x * ds; acc.y += v.y * ds; acc.z += v.z * ds; acc.w += v.w * ds;
    }
    const float dn = dinv[n];
    float4 pv = *(const float4*)(pin + (size_t)n * ldin + col);
    float4 o = make_float4(pv.x - acc.x * dn, pv.y - acc.y * dn,
                           pv.z - acc.z * dn, pv.w - acc.w * dn);
    *(float4*)(outp + (size_t)n * 128 + col) = o;
}

// second propagation fused with filter construction
__global__ __launch_bounds__(256) void prop2F_kernel(
    const float* __restrict__ p1,
    const float* __restrict__ p0, int ld0,
    const int* __restrict__ csr, const int* __restrict__ off,
    const float* __restrict__ dinv, float* __restrict__ F)
{
    const int n = blockIdx.x * 8 + (threadIdx.x >> 5);
    if (n >= CN) return;
    const int lane = threadIdx.x & 31;
    const int col = lane * 4;
    float4 acc = make_float4(0.f, 0.f, 0.f, 0.f);
    const int s0 = off[n], s1 = off[n + 1];
    for (int e = s0; e < s1; e++) {
        int sn = csr[e];
        float ds = __ldg(&dinv[sn]);
        float4 v = *(const float4*)(p1 + (size_t)sn * 128 + col);
        acc.x += v.x * ds; acc.y += v.y * ds; acc.z += v.z * ds; acc.w += v.w * ds;
    }
    const float dn = dinv[n];
    float4 b = *(const float4*)(p1 + (size_t)n * 128 + col);
    float4 a = *(const float4*)(p0 + (size_t)n * ld0 + col);
    float4 c = make_float4(b.x - acc.x * dn, b.y - acc.y * dn,
                           b.z - acc.z * dn, b.w - acc.w * dn);
    float* Fb = F + (size_t)n * 640 + col;
    float4 f0 = make_float4(0.8f * a.x - 0.5f * b.x, 0.8f * a.y - 0.5f * b.y,
                            0.8f * a.z - 0.5f * b.z, 0.8f * a.w - 0.5f * b.w);
    float4 f1 = make_float4(3.0f * a.x - 3.0f * b.x + 0.75f * c.x,
                            3.0f * a.y - 3.0f * b.y + 0.75f * c.y,
                            3.0f * a.z - 3.0f * b.z + 0.75f * c.z,
                            3.0f * a.w - 3.0f * b.w + 0.75f * c.w);
    float4 f2 = make_float4(3.0f * b.x - 1.5f * c.x, 3.0f * b.y - 1.5f * c.y,
                            3.0f * b.z - 1.5f * c.z, 3.0f * b.w - 1.5f * c.w);
    float4 f3 = make_float4(0.75f * c.x, 0.75f * c.y, 0.75f * c.z, 0.75f * c.w);
    float4 f4 = make_float4(-0.2f * a.x + 0.5f * b.x, -0.2f * a.y + 0.5f * b.y,
                            -0.2f * a.z + 0.5f * b.z, -0.2f * a.w + 0.5f * b.w);
    *(float4*)(Fb)       = f0;
    *(float4*)(Fb + 128) = f1;
    *(float4*)(Fb + 256) = f2;
    *(float4*)(Fb + 384) = f3;
    *(float4*)(Fb + 512) = f4;
}

// softmax over 5 per-node scores; res = sum_f soft_f * F_f
__global__ void attn_res_kernel(const float* __restrict__ score, const float* __restrict__ F,
                                float* __restrict__ res)
{
    size_t gid = (size_t)blockIdx.x * blockDim.x + threadIdx.x;
    int n = (int)(gid >> 5);
    int lane = (int)(gid & 31);
    if (n >= CN) return;
    float sc[5];
#pragma unroll
    for (int f = 0; f < 5; f++) sc[f] = score[(size_t)n * 5 + f];
    float mx = sc[0];
#pragma unroll
    for (int f = 1; f < 5; f++) mx = fmaxf(mx, sc[f]);
    float e[5], s = 0.f;
#pragma unroll
    for (int f = 0; f < 5; f++) { e[f] = expf(sc[f] - mx); s += e[f]; }
    float inv = 1.f / s;
    const float* Fb = F + (size_t)n * 640;
    const int col = lane * 4;
    float4 r = make_float4(0.f, 0.f, 0.f, 0.f);
#pragma unroll
    for (int f = 0; f < 5; f++) {
        float4 v = *(const float4*)(Fb + f * 128 + col);
        float w = e[f];
        r.x += w * v.x; r.y += w * v.y; r.z += w * v.z; r.w += w * v.w;
    }
    r.x *= inv; r.y *= inv; r.z *= inv; r.w *= inv;
    *(float4*)(res + (size_t)n * 128 + col) = r;
}

// out[n, c] = big[n, :] . W6[c, :] + b6[c], warp per node
__global__ void final_kernel(const float* __restrict__ big, const float* __restrict__ W6,
                             const float* __restrict__ b6, float* __restrict__ out)
{
    size_t gid = (size_t)blockIdx.x * blockDim.x + threadIdx.x;
    int n = (int)(gid >> 5);
    int lane = (int)(gid & 31);
    if (n >= CN) return;
    const float* row = big + (size_t)n * 768;
#pragma unroll
    for (int c = 0; c < 2; c++) {
        float a = 0.f;
        for (int j = lane; j < 768; j += 32) a += row[j] * W6[c * 768 + j];
#pragma unroll
        for (int off = 16; off; off >>= 1) a += __shfl_xor_sync(0xffffffffu, a, off);
        if (lane == 0) out[(size_t)n * 2 + c] = a + b6[c];
    }
}

// ---------------- orchestration ----------------
extern "C" void kernel_launch(void* const* d_in, const int* in_sizes, int n_in,
                              void* d_out, int out_size)
{
    const float* voc    = (const float*)d_in[0];
    const float* sms    = (const float*)d_in[1];
    const float* pers   = (const float*)d_in[2];
    const float* Wih_v  = (const float*)d_in[3];
    const float* Whh_v  = (const float*)d_in[4];
    const float* bih_v  = (const float*)d_in[5];
    const float* bhh_v  = (const float*)d_in[6];
    const float* Wih_s  = (const float*)d_in[7];
    const float* Whh_s  = (const float*)d_in[8];
    const float* bih_s  = (const float*)d_in[9];
    const float* bhh_s  = (const float*)d_in[10];
    const float* W_lin  = (const float*)d_in[11];
    const float* b_lin  = (const float*)d_in[12];
    const float* W_lin1 = (const float*)d_in[13];
    const float* b_lin1 = (const float*)d_in[14];
    const float* W_pers = (const float*)d_in[15];
    const float* b_pers = (const float*)d_in[16];
    const float* W_lin2 = (const float*)d_in[17];
    const float* b_lin2 = (const float*)d_in[18];
    const float* W_lin3 = (const float*)d_in[19];
    const float* b_lin3 = (const float*)d_in[20];
    const float* W_lin4 = (const float*)d_in[21];
    const float* b_lin4 = (const float*)d_in[22];
    const float* W_lin5 = (const float*)d_in[23];
    const float* b_lin5 = (const float*)d_in[24];
    const float* Wf1    = (const float*)d_in[25];
    const float* bf1    = (const float*)d_in[26];
    const float* Wf2    = (const float*)d_in[27];
    const float* W_lin6 = (const float*)d_in[28];
    const float* b_lin6 = (const float*)d_in[29];
    const int*   src    = (const int*)d_in[30];
    const int*   dst    = (const int*)d_in[31];
    float* out = (float*)d_out;

    float* S = nullptr;
    cudaGetSymbolAddress((void**)&S, g_scratch);
    int* csr = nullptr; cudaGetSymbolAddress((void**)&csr, g_csr);
    int* offp = nullptr; cudaGetSymbolAddress((void**)&offp, g_off);
    int* curp = nullptr; cudaGetSymbolAddress((void**)&curp, g_cur);

    // prep: interleaved LSTM weights/biases, zero states (HV0,HV1,HS0,HS1,CV,CS)
    prep_kernel<<<(256 * 128 + 255) / 256, 256>>>(Wih_v, Whh_v, bih_v, bhh_v,
                                                  Wih_s, Whh_s, bih_s, bhh_s, S);
    zero_kernel<<<4096, 256>>>(S + OFF_HV0, (size_t)6 * CN * 64);

    // ---- LSTMs: 16 steps, both LSTMs per launch, fused GEMM+cell ----
    dim3 lgrid(4, (CN + 127) / 128);
    for (int t = 0; t < CT; t++) {
        const float* hv_in  = S + ((t & 1) ? OFF_HV1 : OFF_HV0);
        float*       hv_out = S + ((t & 1) ? OFF_HV0 : OFF_HV1);
        const float* hs_in  = S + ((t & 1) ? OFF_HS1 : OFF_HS0);
        float*       hs_out = S + ((t & 1) ? OFF_HS0 : OFF_HS1);
        lstm_step2_kernel<<<lgrid, 256>>>(voc + (size_t)t * 64, sms + (size_t)t * 64, CT * 64,
                                          hv_in, hs_in,
                                          S + OFF_WCV, S + OFF_WCS,
                                          S + OFF_BCV, S + OFF_BCS,
                                          S + OFF_CV, S + OFF_CS,
                                          hv_out, hs_out);
    }
    // final h is in HV0 / HS0 (16 steps, even)

    // ---- projections ----
    gemm(S + OFF_HV0, 64, 64, S + OFF_HV0, 64, W_lin, b_lin,
         S + OFF_XCAT + 0, 512, CN, 128, 64, 1);
    gemm(S + OFF_HS0, 64, 64, S + OFF_HS0, 64, W_lin1, b_lin1,
         S + OFF_XCAT + 256, 512, CN, 128, 64, 1);
    gemm(pers, 32, 32, pers, 32, W_pers, b_pers,
         S + OFF_XCAT + 128, 512, CN, 128, 32, 1);
    copy_xp_kernel<<<((size_t)CN * 128 + 255) / 256, 256>>>(S);

    gemm(S + OFF_XCAT, 512, 256, S + OFF_XCAT, 512, W_lin2, b_lin2,
         S + OFF_BIG + 384, 768, CN, 128, 256, 1);
    gemm(S + OFF_XCAT + 256, 512, 256, S + OFF_XCAT + 256, 512, W_lin3, b_lin3,
         S + OFF_BIG + 512, 768, CN, 128, 256, 1);
    gemm(S + OFF_XCAT, 512, 512, S + OFF_XCAT, 512, W_lin4, b_lin4,
         S + OFF_BIG + 640, 768, CN, 128, 512, 1);

    // ---- relation graphs (CSR gather-based propagation) ----
    const int pgrid = (CN + 7) / 8;
    for (int r = 0; r < CR; r++) {
        const int* sr = src + (size_t)r * CE;
        const int* dr = dst + (size_t)r * CE;
        const float* p0 = S + OFF_BIG + 384 + 128 * r;  // lda 768

        zero_kernel<<<256, 256>>>(S + OFF_DEG, (size_t)CN);
        deg_kernel<<<(CE + 255) / 256, 256>>>(dr, S + OFF_DEG);
        dinv_kernel<<<(CN + 255) / 256, 256>>>(S);
        scan_kernel<<<1, 1024>>>(S + OFF_DEG, offp, curp);
        fill_kernel<<<(CE + 255) / 256, 256>>>(sr, dr, curp, csr);

        prop_kernel<<<pgrid, 256>>>(p0, 768, csr, offp, S + OFF_DINV, S + OFF_P1);
        prop2F_kernel<<<pgrid, 256>>>(S + OFF_P1, p0, 768, csr, offp,
                                      S + OFF_DINV, S + OFF_F);

        // scores = w2 . tanh(F @ Wf1^T + bf1) fused (Y never materialized)
        {
            dim3 sgrid(1, (CN * 5 + 127) / 128);
            sgemm_score_kernel<<<sgrid, 256>>>(S + OFF_F, 128,
                                               Wf1 + (size_t)r * 128 * 128,
                                               bf1 + (size_t)r * 128,
                                               Wf2 + (size_t)r * 128,
                                               S + OFF_SC, CN * 5);
        }

        attn_res_kernel<<<((size_t)CN * 32 + 255) / 256, 256>>>(S + OFF_SC, S + OFF_F,
                                                                S + OFF_RES);

        // hall_r = act(res @ W_lin5[r]^T + b_lin5[r]) -> big cols [128r, 128r+128)
        gemm(S + OFF_RES, 128, 128, S + OFF_RES, 128,
             W_lin5 + (size_t)r * 128 * 128, b_lin5 + (size_t)r * 128,
             S + OFF_BIG + 128 * r, 768, CN, 128, 128, 1);
    }

    // ---- final head ----
    final_kernel<<<((size_t)CN * 32 + 255) / 256, 256>>>(S + OFF_BIG, W_lin6, b_lin6, out);
}